// round 16
// baseline (speedup 1.0000x reference)
#include <cuda_runtime.h>
#include <cuda_fp16.h>
#include <stdint.h>

#define B_  4
#define T_  2048
#define H_  1024
#define NH_ 16
#define HD_ 64
#define M_  (B_ * T_)   // 8192

#define LOG2E 1.4426950408889634f
#define ONES2 0x3C003C00u   // half2 {1,1}

// fp16 scratch: projected Q(pre-scaled by 0.125*log2e)/K/V, converted X and W.
__device__ __half g_Q[M_ * H_];
__device__ __half g_K[M_ * H_];
__device__ __half g_V[M_ * H_];
__device__ __half g_X16[M_ * H_];
__device__ __half g_W16[3 * H_ * H_];
__device__ float  g_ML[B_ * T_];     // mask * LOG2E

// ===========================================================================
// PTX helpers (mma.sync / ldmatrix / cp.async — harness targets plain sm_100)
// ===========================================================================
__device__ __forceinline__ void mma_f16(float d[4], const uint32_t a[4], const uint32_t b[2]) {
    asm volatile(
        "mma.sync.aligned.m16n8k16.row.col.f32.f16.f16.f32 "
        "{%0,%1,%2,%3}, {%4,%5,%6,%7}, {%8,%9}, {%0,%1,%2,%3};\n"
        : "+f"(d[0]), "+f"(d[1]), "+f"(d[2]), "+f"(d[3])
        : "r"(a[0]), "r"(a[1]), "r"(a[2]), "r"(a[3]), "r"(b[0]), "r"(b[1]));
}
__device__ __forceinline__ void ldsm4(uint32_t addr, uint32_t &r0, uint32_t &r1,
                                      uint32_t &r2, uint32_t &r3) {
    asm volatile("ldmatrix.sync.aligned.m8n8.x4.shared.b16 {%0,%1,%2,%3}, [%4];"
                 : "=r"(r0), "=r"(r1), "=r"(r2), "=r"(r3) : "r"(addr));
}
__device__ __forceinline__ void ldsm4t(uint32_t addr, uint32_t &r0, uint32_t &r1,
                                       uint32_t &r2, uint32_t &r3) {
    asm volatile("ldmatrix.sync.aligned.m8n8.x4.trans.shared.b16 {%0,%1,%2,%3}, [%4];"
                 : "=r"(r0), "=r"(r1), "=r"(r2), "=r"(r3) : "r"(addr));
}
__device__ __forceinline__ void cp16(uint32_t saddr, const void* gaddr) {
    asm volatile("cp.async.cg.shared.global [%0], [%1], 16;" :: "r"(saddr), "l"(gaddr));
}
__device__ __forceinline__ void cp4(uint32_t saddr, const void* gaddr) {
    asm volatile("cp.async.ca.shared.global [%0], [%1], 4;" :: "r"(saddr), "l"(gaddr));
}
__device__ __forceinline__ void cp_commit() {
    asm volatile("cp.async.commit_group;" ::: "memory");
}
template <int N>
__device__ __forceinline__ void cp_wait() {
    asm volatile("cp.async.wait_group %0;" :: "n"(N) : "memory");
}
__device__ __forceinline__ uint32_t h2exp2(uint32_t x) {
    uint32_t r;
    asm("ex2.approx.f16x2 %0, %1;" : "=r"(r) : "r"(x));
    return r;
}

// ===========================================================================
// Prep kernels
// ===========================================================================
__global__ __launch_bounds__(256) void cvtX(
    const float* __restrict__ src, __half* __restrict__ dst, int n8)
{
    int i = blockIdx.x * blockDim.x + threadIdx.x;
    if (i < n8) {
        const float4* s4 = (const float4*)src + (size_t)i * 2;
        float4 a = s4[0], b = s4[1];
        __half2 h[4] = { __floats2half2_rn(a.x, a.y), __floats2half2_rn(a.z, a.w),
                         __floats2half2_rn(b.x, b.y), __floats2half2_rn(b.z, b.w) };
        *((uint4*)dst + i) = *(uint4*)h;
    }
}
__global__ __launch_bounds__(256) void cvtW(
    const float* __restrict__ Wq, const float* __restrict__ Wk,
    const float* __restrict__ Wv)
{
    const int z = blockIdx.z;
    const float* src = (z == 0) ? Wq : (z == 1) ? Wk : Wv;
    __half* dst = g_W16 + (size_t)z * H_ * H_;
    int i = blockIdx.x * blockDim.x + threadIdx.x;
    const float4* s4 = (const float4*)src + (size_t)i * 2;
    float4 a = s4[0], b = s4[1];
    __half2 h[4] = { __floats2half2_rn(a.x, a.y), __floats2half2_rn(a.z, a.w),
                     __floats2half2_rn(b.x, b.y), __floats2half2_rn(b.z, b.w) };
    *((uint4*)dst + i) = *(uint4*)h;
}
__global__ __launch_bounds__(256) void prepMask(const float* __restrict__ m)
{
    int i = blockIdx.x * blockDim.x + threadIdx.x;
    g_ML[i] = m[i] * LOG2E;
}

// ===========================================================================
// QKV GEMM — R11 pipeline, with per-warp kcc rotation to de-phase the
// post-barrier LDSM convoy (warps hit smem port / tensor pipe staggered).
// 128x128 tiles, 8 warps (4m x 2n), warp 32x64, K-chunks of 64,
// 3-slot cp.async, single barrier per iteration.
// ===========================================================================
#define GLD    72
#define GSTG   (128 * GLD)
#define NSTG   3
#define NCHUNK 16
#define GEMM_SMEM (2 * NSTG * GSTG * 2)    // 110592 bytes

__global__ __launch_bounds__(256, 2) void qkv_gemm_fp16(
    const float* __restrict__ bq, const float* __restrict__ bk,
    const float* __restrict__ bv)
{
    extern __shared__ __align__(16) __half smh[];
    const uint32_t sb = (uint32_t)__cvta_generic_to_shared(smh);

    const int z = blockIdx.z;
    const __half* Wp  = g_W16 + (size_t)z * H_ * H_;
    const float* bias = (z == 0) ? bq : (z == 1) ? bk : bv;
    __half* out       = (z == 0) ? g_Q : (z == 1) ? g_K : g_V;
    const float scale = (z == 0) ? 0.125f * LOG2E : 1.0f;

    const int tid  = threadIdx.x;
    const int lane = tid & 31;
    const int wid  = tid >> 5;
    const int bm   = blockIdx.y * 128;
    const int bn   = blockIdx.x * 128;
    const int moff = (wid & 3) * 32;
    const int noff = (wid >> 2) * 64;
    const int g    = lane >> 2;
    const int c    = lane & 3;
    const int arow = ((lane >> 3) & 1) * 8 + (lane & 7);
    const int acol = (lane >> 4) * 8;
    const int brow = ((lane >> 4) << 3) + (lane & 7);
    const int bcol = ((lane >> 3) & 1) * 8;
    const int wrot = wid & 3;              // per-warp phase rotation

    float d[2][8][4];
    #pragma unroll
    for (int mt = 0; mt < 2; mt++)
        #pragma unroll
        for (int nt = 0; nt < 8; nt++)
            #pragma unroll
            for (int e = 0; e < 4; e++) d[mt][nt][e] = 0.f;

    auto issue = [&](int kc, int s) {
        const int k0 = kc * 64;
        #pragma unroll
        for (int i = 0; i < 4; i++) {
            int u = tid + 256 * i;
            int row = u >> 3, c8 = u & 7;
            cp16(sb + (s * GSTG + row * GLD + c8 * 8) * 2,
                 g_X16 + (size_t)(bm + row) * H_ + k0 + c8 * 8);
            cp16(sb + ((NSTG + s) * GSTG + row * GLD + c8 * 8) * 2,
                 Wp + (size_t)(bn + row) * H_ + k0 + c8 * 8);
        }
        cp_commit();
    };

    issue(0, 0);
    issue(1, 1);

    for (int kc = 0; kc < NCHUNK; kc++) {
        const int s = kc % NSTG;
        if (kc == NCHUNK - 1) cp_wait<0>(); else cp_wait<1>();
        __syncthreads();
        if (kc + 2 < NCHUNK) issue(kc + 2, (kc + 2) % NSTG);

        const uint32_t ab = sb + (s * GSTG) * 2;
        const uint32_t bb = sb + ((NSTG + s) * GSTG) * 2;
        #pragma unroll
        for (int kccr = 0; kccr < 4; kccr++) {
            const int kcc = (kccr + wrot) & 3;     // staggered per warp
            const int kk = kcc * 16;
            uint32_t a[2][4];
            #pragma unroll
            for (int mt = 0; mt < 2; mt++) {
                int row = moff + mt * 16 + arow;
                ldsm4(ab + (row * GLD + kk + acol) * 2,
                      a[mt][0], a[mt][1], a[mt][2], a[mt][3]);
            }
            #pragma unroll
            for (int np = 0; np < 4; np++) {
                uint32_t b0, b1, b2, b3;
                int row = noff + np * 16 + brow;
                ldsm4(bb + (row * GLD + kk + bcol) * 2, b0, b1, b2, b3);
                uint32_t bl[2] = { b0, b1 }, bh[2] = { b2, b3 };
                #pragma unroll
                for (int mt = 0; mt < 2; mt++) {
                    mma_f16(d[mt][2 * np],     a[mt], bl);
                    mma_f16(d[mt][2 * np + 1], a[mt], bh);
                }
            }
        }
    }

    #pragma unroll
    for (int mt = 0; mt < 2; mt++) {
        int row = bm + moff + mt * 16 + g;
        #pragma unroll
        for (int nt = 0; nt < 8; nt++) {
            int col = bn + noff + nt * 8 + 2 * c;
            float2 bv2 = *(const float2*)(bias + col);
            __half2 lo = __floats2half2_rn((d[mt][nt][0] + bv2.x) * scale,
                                           (d[mt][nt][1] + bv2.y) * scale);
            __half2 hi = __floats2half2_rn((d[mt][nt][2] + bv2.x) * scale,
                                           (d[mt][nt][3] + bv2.y) * scale);
            *(__half2*)(out + (size_t)row * H_ + col)       = lo;
            *(__half2*)(out + (size_t)(row + 8) * H_ + col) = hi;
        }
    }
}

// ===========================================================================
// Flash attention — R15 math with per-warp np/dp rotation (bit-exact
// accumulator permutation) to de-phase post-barrier LDSM bursts.
// ===========================================================================
#define LQH 72

__global__ __launch_bounds__(128) void attn_fp16(float* __restrict__ out)
{
    __shared__ __align__(16) __half Qs[64 * LQH];
    __shared__ __align__(16) __half Ks[2][64 * LQH];
    __shared__ __align__(16) __half Vs[2][64 * LQH];
    __shared__ float Ms[2][64];

    const int tid  = threadIdx.x;
    const int lane = tid & 31;
    const int wid  = tid >> 5;
    const int qb   = (T_ / 64 - 1) - blockIdx.x;   // reversed: heavy first
    const int h    = blockIdx.y;
    const int b    = blockIdx.z;
    const int g    = lane >> 2;
    const int c    = lane & 3;
    const int qrow0 = qb * 64 + wid * 16 + g;
    const int wrot = wid & 3;

    const uint32_t qs_base = (uint32_t)__cvta_generic_to_shared(Qs);
    const uint32_t ks_base = (uint32_t)__cvta_generic_to_shared(&Ks[0][0]);
    const uint32_t vs_base = (uint32_t)__cvta_generic_to_shared(&Vs[0][0]);
    const uint32_t ms_base = (uint32_t)__cvta_generic_to_shared(&Ms[0][0]);
    const int arow = ((lane >> 3) & 1) * 8 + (lane & 7);
    const int acol = (lane >> 4) * 8;
    const int brow = ((lane >> 4) << 3) + (lane & 7);
    const int bcol = ((lane >> 3) & 1) * 8;

    const size_t hdoff = (size_t)(b * T_) * H_ + h * HD_;
    const __half* kgb = g_K + hdoff;
    const __half* vgb = g_V + hdoff;

    auto issue = [&](int kb, int buf) {
        const __half* kg = kgb + (size_t)kb * 64 * H_;
        const __half* vg = vgb + (size_t)kb * 64 * H_;
        const uint32_t koff = ks_base + buf * (64 * LQH * 2);
        const uint32_t voff = vs_base + buf * (64 * LQH * 2);
        #pragma unroll
        for (int i = 0; i < 4; i++) {
            int u = tid + 128 * i;
            int row = u >> 3, c8 = u & 7;
            cp16(koff + (row * LQH + c8 * 8) * 2, kg + (size_t)row * H_ + c8 * 8);
            cp16(voff + (row * LQH + c8 * 8) * 2, vg + (size_t)row * H_ + c8 * 8);
        }
        if (tid < 64)
            cp4(ms_base + (buf * 64 + tid) * 4, g_ML + (size_t)b * T_ + kb * 64 + tid);
        cp_commit();
    };

    const __half* qg = g_Q + hdoff + (size_t)qb * 64 * H_;
    issue(0, 0);
    #pragma unroll
    for (int i = 0; i < 4; i++) {
        int idx = tid + 128 * i;
        int row = idx >> 3, c8 = idx & 7;
        *(uint4*)&Qs[row * LQH + c8 * 8] =
            *(const uint4*)(qg + (size_t)row * H_ + c8 * 8);
    }
    __syncthreads();

    uint32_t qa[4][4];
    #pragma unroll
    for (int kc = 0; kc < 4; kc++)
        ldsm4(qs_base + ((wid * 16 + arow) * LQH + kc * 16 + acol) * 2,
              qa[kc][0], qa[kc][1], qa[kc][2], qa[kc][3]);

    float o[8][4];
    #pragma unroll
    for (int nt = 0; nt < 8; nt++)
        #pragma unroll
        for (int e = 0; e < 4; e++) o[nt][e] = 0.f;
    float lacc[4] = { 0.f, 0.f, 0.f, 0.f };
    float m0 = -1e30f, m1 = -1e30f;
    const uint32_t onesb[2] = { ONES2, ONES2 };

    for (int kb = 0; kb <= qb; kb++) {
        const int buf = kb & 1;
        cp_wait<0>();
        __syncthreads();
        if (kb < qb) issue(kb + 1, buf ^ 1);

        const uint32_t kbb = ks_base + buf * (64 * LQH * 2);
        const uint32_t vbb = vs_base + buf * (64 * LQH * 2);
        const float* MsB = Ms[buf];

        // ---- S = Q K^T (np rotated per warp; bit-exact) ----
        float s[8][4];
        #pragma unroll
        for (int nt = 0; nt < 8; nt++)
            #pragma unroll
            for (int e = 0; e < 4; e++) s[nt][e] = 0.f;

        #pragma unroll
        for (int kc = 0; kc < 4; kc++) {
            const int kk = kc * 16;
            #pragma unroll
            for (int npr = 0; npr < 4; npr++) {
                const int np = (npr + wrot) & 3;
                uint32_t b0, b1, b2, b3;
                ldsm4(kbb + ((np * 16 + brow) * LQH + kk + bcol) * 2, b0, b1, b2, b3);
                uint32_t bl[2] = { b0, b1 }, bh[2] = { b2, b3 };
                mma_f16(s[2 * np],     qa[kc], bl);
                mma_f16(s[2 * np + 1], qa[kc], bh);
            }
        }

        // ---- mask + online softmax (exp2 domain) ----
        float rmax0 = -1e30f, rmax1 = -1e30f;
        #pragma unroll
        for (int nt = 0; nt < 8; nt++) {
            int lc = nt * 8 + 2 * c;
            float mk0 = MsB[lc], mk1 = MsB[lc + 1];
            s[nt][0] += mk0; s[nt][1] += mk1;
            s[nt][2] += mk0; s[nt][3] += mk1;
            if (kb == qb) {
                int col = kb * 64 + lc;
                if (col     > qrow0)     s[nt][0] = -1e30f;
                if (col + 1 > qrow0)     s[nt][1] = -1e30f;
                if (col     > qrow0 + 8) s[nt][2] = -1e30f;
                if (col + 1 > qrow0 + 8) s[nt][3] = -1e30f;
            }
            rmax0 = fmaxf(rmax0, fmaxf(s[nt][0], s[nt][1]));
            rmax1 = fmaxf(rmax1, fmaxf(s[nt][2], s[nt][3]));
        }
        rmax0 = fmaxf(rmax0, __shfl_xor_sync(0xffffffffu, rmax0, 1));
        rmax0 = fmaxf(rmax0, __shfl_xor_sync(0xffffffffu, rmax0, 2));
        rmax1 = fmaxf(rmax1, __shfl_xor_sync(0xffffffffu, rmax1, 1));
        rmax1 = fmaxf(rmax1, __shfl_xor_sync(0xffffffffu, rmax1, 2));

        float mn0 = fmaxf(m0, rmax0), mn1 = fmaxf(m1, rmax1);
        if (__any_sync(0xffffffffu, (mn0 > m0) | (mn1 > m1))) {
            float cr0 = exp2f(m0 - mn0), cr1 = exp2f(m1 - mn1);
            #pragma unroll
            for (int nt = 0; nt < 8; nt++) {
                o[nt][0] *= cr0; o[nt][1] *= cr0;
                o[nt][2] *= cr1; o[nt][3] *= cr1;
            }
            lacc[0] *= cr0; lacc[2] *= cr1;
            m0 = mn0; m1 = mn1;
        }

        // ---- P = 2^(s-m) directly in fp16 pairs ----
        uint32_t ph[8][2];
        #pragma unroll
        for (int nt = 0; nt < 8; nt++) {
            __half2 t01 = __floats2half2_rn(s[nt][0] - m0, s[nt][1] - m0);
            __half2 t23 = __floats2half2_rn(s[nt][2] - m1, s[nt][3] - m1);
            ph[nt][0] = h2exp2(*(uint32_t*)&t01);
            ph[nt][1] = h2exp2(*(uint32_t*)&t23);
        }

        // ---- O += P V ; l += P * ones (dp rotated per warp; bit-exact) ----
        #pragma unroll
        for (int jc = 0; jc < 4; jc++) {
            uint32_t a[4] = { ph[2 * jc][0], ph[2 * jc][1],
                              ph[2 * jc + 1][0], ph[2 * jc + 1][1] };
            mma_f16(lacc, a, onesb);
            #pragma unroll
            for (int dpr = 0; dpr < 4; dpr++) {
                const int dp = (dpr + wrot) & 3;
                uint32_t b0, b1, b2, b3;
                ldsm4t(vbb + ((jc * 16 + arow) * LQH + dp * 16 + acol) * 2,
                       b0, b1, b2, b3);
                uint32_t bl[2] = { b0, b1 }, bh[2] = { b2, b3 };
                mma_f16(o[2 * dp],     a, bl);
                mma_f16(o[2 * dp + 1], a, bh);
            }
        }
    }

    float inv0 = 1.f / lacc[0], inv1 = 1.f / lacc[2];
    float* og = out + ((size_t)(b * T_) + (size_t)qb * 64 + wid * 16 + g) * H_ + h * HD_;
    #pragma unroll
    for (int nt = 0; nt < 8; nt++) {
        int lc = nt * 8 + 2 * c;
        float2 w0, w1;
        w0.x = o[nt][0] * inv0; w0.y = o[nt][1] * inv0;
        w1.x = o[nt][2] * inv1; w1.y = o[nt][3] * inv1;
        *(float2*)(og + lc)          = w0;
        *(float2*)(og + 8 * H_ + lc) = w1;
    }
}

// ===========================================================================
// Launch
// ===========================================================================
extern "C" void kernel_launch(void* const* d_in, const int* in_sizes, int n_in,
                              void* d_out, int out_size)
{
    const float* x    = (const float*)d_in[0];
    const float* mask = (const float*)d_in[1];
    const float* Wq   = (const float*)d_in[2];
    const float* bq   = (const float*)d_in[3];
    const float* Wk   = (const float*)d_in[4];
    const float* bk   = (const float*)d_in[5];
    const float* Wv   = (const float*)d_in[6];
    const float* bv   = (const float*)d_in[7];
    float* out = (float*)d_out;

    __half *X16p;
    cudaGetSymbolAddress((void**)&X16p, g_X16);

    cudaFuncSetAttribute(qkv_gemm_fp16, cudaFuncAttributeMaxDynamicSharedMemorySize,
                         GEMM_SMEM);

    cvtX<<<(M_ * H_ / 8 + 255) / 256, 256>>>(x, X16p, M_ * H_ / 8);
    dim3 wgrid(H_ * H_ / 8 / 256, 1, 3);
    cvtW<<<wgrid, 256>>>(Wq, Wk, Wv);
    prepMask<<<B_ * T_ / 256, 256>>>(mask);

    dim3 ggrid(H_ / 128, M_ / 128, 3);   // (8, 64, 3)
    qkv_gemm_fp16<<<ggrid, 256, GEMM_SMEM>>>(bq, bk, bv);

    dim3 agrid(T_ / 64, NH_, B_);        // (32, 16, 4)
    attn_fp16<<<agrid, 128>>>(out);
}

// round 17
// speedup vs baseline: 3.6330x; 3.6330x over previous
#include <cuda_runtime.h>
#include <cuda_fp16.h>
#include <stdint.h>

#define B_  4
#define T_  2048
#define H_  1024
#define NH_ 16
#define HD_ 64
#define M_  (B_ * T_)   // 8192

#define LOG2E 1.4426950408889634f
#define ONES2 0x3C003C00u   // half2 {1,1}

// fp16 scratch: projected Q(pre-scaled by 0.125*log2e)/K/V, converted X and W.
__device__ __half g_Q[M_ * H_];
__device__ __half g_K[M_ * H_];
__device__ __half g_V[M_ * H_];
__device__ __half g_X16[M_ * H_];
__device__ __half g_W16[3 * H_ * H_];
__device__ float  g_ML[B_ * T_];     // mask * LOG2E

// ===========================================================================
// PTX helpers (mma.sync / ldmatrix / cp.async — harness targets plain sm_100)
// ===========================================================================
__device__ __forceinline__ void mma_f16(float d[4], const uint32_t a[4], const uint32_t b[2]) {
    asm volatile(
        "mma.sync.aligned.m16n8k16.row.col.f32.f16.f16.f32 "
        "{%0,%1,%2,%3}, {%4,%5,%6,%7}, {%8,%9}, {%0,%1,%2,%3};\n"
        : "+f"(d[0]), "+f"(d[1]), "+f"(d[2]), "+f"(d[3])
        : "r"(a[0]), "r"(a[1]), "r"(a[2]), "r"(a[3]), "r"(b[0]), "r"(b[1]));
}
__device__ __forceinline__ void ldsm4(uint32_t addr, uint32_t &r0, uint32_t &r1,
                                      uint32_t &r2, uint32_t &r3) {
    asm volatile("ldmatrix.sync.aligned.m8n8.x4.shared.b16 {%0,%1,%2,%3}, [%4];"
                 : "=r"(r0), "=r"(r1), "=r"(r2), "=r"(r3) : "r"(addr));
}
__device__ __forceinline__ void ldsm4t(uint32_t addr, uint32_t &r0, uint32_t &r1,
                                       uint32_t &r2, uint32_t &r3) {
    asm volatile("ldmatrix.sync.aligned.m8n8.x4.trans.shared.b16 {%0,%1,%2,%3}, [%4];"
                 : "=r"(r0), "=r"(r1), "=r"(r2), "=r"(r3) : "r"(addr));
}
__device__ __forceinline__ void cp16(uint32_t saddr, const void* gaddr) {
    asm volatile("cp.async.cg.shared.global [%0], [%1], 16;" :: "r"(saddr), "l"(gaddr));
}
__device__ __forceinline__ void cp4(uint32_t saddr, const void* gaddr) {
    asm volatile("cp.async.ca.shared.global [%0], [%1], 4;" :: "r"(saddr), "l"(gaddr));
}
__device__ __forceinline__ void cp_commit() {
    asm volatile("cp.async.commit_group;" ::: "memory");
}
template <int N>
__device__ __forceinline__ void cp_wait() {
    asm volatile("cp.async.wait_group %0;" :: "n"(N) : "memory");
}
__device__ __forceinline__ uint32_t h2exp2(uint32_t x) {
    uint32_t r;
    asm("ex2.approx.f16x2 %0, %1;" : "=r"(r) : "r"(x));
    return r;
}

// ===========================================================================
// Prep kernels
// ===========================================================================
__global__ __launch_bounds__(256) void cvtX(
    const float* __restrict__ src, __half* __restrict__ dst, int n8)
{
    int i = blockIdx.x * blockDim.x + threadIdx.x;
    if (i < n8) {
        const float4* s4 = (const float4*)src + (size_t)i * 2;
        float4 a = s4[0], b = s4[1];
        __half2 h[4] = { __floats2half2_rn(a.x, a.y), __floats2half2_rn(a.z, a.w),
                         __floats2half2_rn(b.x, b.y), __floats2half2_rn(b.z, b.w) };
        *((uint4*)dst + i) = *(uint4*)h;
    }
}
__global__ __launch_bounds__(256) void cvtW(
    const float* __restrict__ Wq, const float* __restrict__ Wk,
    const float* __restrict__ Wv)
{
    const int z = blockIdx.z;
    const float* src = (z == 0) ? Wq : (z == 1) ? Wk : Wv;
    __half* dst = g_W16 + (size_t)z * H_ * H_;
    int i = blockIdx.x * blockDim.x + threadIdx.x;
    const float4* s4 = (const float4*)src + (size_t)i * 2;
    float4 a = s4[0], b = s4[1];
    __half2 h[4] = { __floats2half2_rn(a.x, a.y), __floats2half2_rn(a.z, a.w),
                     __floats2half2_rn(b.x, b.y), __floats2half2_rn(b.z, b.w) };
    *((uint4*)dst + i) = *(uint4*)h;
}
__global__ __launch_bounds__(256) void prepMask(const float* __restrict__ m)
{
    int i = blockIdx.x * blockDim.x + threadIdx.x;
    g_ML[i] = m[i] * LOG2E;
}

// ===========================================================================
// QKV GEMM — R16 version (measured 176.0us): per-warp kcc rotation de-phases
// the post-barrier LDSM convoy. Rotation feeds ONLY address math (kk);
// accumulator d[][] indices stay compile-time. 128x128 tiles, 8 warps,
// warp 32x64, K-chunks of 64, 3-slot cp.async, single barrier/iteration.
// ===========================================================================
#define GLD    72
#define GSTG   (128 * GLD)
#define NSTG   3
#define NCHUNK 16
#define GEMM_SMEM (2 * NSTG * GSTG * 2)    // 110592 bytes

__global__ __launch_bounds__(256, 2) void qkv_gemm_fp16(
    const float* __restrict__ bq, const float* __restrict__ bk,
    const float* __restrict__ bv)
{
    extern __shared__ __align__(16) __half smh[];
    const uint32_t sb = (uint32_t)__cvta_generic_to_shared(smh);

    const int z = blockIdx.z;
    const __half* Wp  = g_W16 + (size_t)z * H_ * H_;
    const float* bias = (z == 0) ? bq : (z == 1) ? bk : bv;
    __half* out       = (z == 0) ? g_Q : (z == 1) ? g_K : g_V;
    const float scale = (z == 0) ? 0.125f * LOG2E : 1.0f;

    const int tid  = threadIdx.x;
    const int lane = tid & 31;
    const int wid  = tid >> 5;
    const int bm   = blockIdx.y * 128;
    const int bn   = blockIdx.x * 128;
    const int moff = (wid & 3) * 32;
    const int noff = (wid >> 2) * 64;
    const int g    = lane >> 2;
    const int c    = lane & 3;
    const int arow = ((lane >> 3) & 1) * 8 + (lane & 7);
    const int acol = (lane >> 4) * 8;
    const int brow = ((lane >> 4) << 3) + (lane & 7);
    const int bcol = ((lane >> 3) & 1) * 8;
    const int wrot = wid & 3;              // per-warp phase rotation (addresses only)

    float d[2][8][4];
    #pragma unroll
    for (int mt = 0; mt < 2; mt++)
        #pragma unroll
        for (int nt = 0; nt < 8; nt++)
            #pragma unroll
            for (int e = 0; e < 4; e++) d[mt][nt][e] = 0.f;

    auto issue = [&](int kc, int s) {
        const int k0 = kc * 64;
        #pragma unroll
        for (int i = 0; i < 4; i++) {
            int u = tid + 256 * i;
            int row = u >> 3, c8 = u & 7;
            cp16(sb + (s * GSTG + row * GLD + c8 * 8) * 2,
                 g_X16 + (size_t)(bm + row) * H_ + k0 + c8 * 8);
            cp16(sb + ((NSTG + s) * GSTG + row * GLD + c8 * 8) * 2,
                 Wp + (size_t)(bn + row) * H_ + k0 + c8 * 8);
        }
        cp_commit();
    };

    issue(0, 0);
    issue(1, 1);

    for (int kc = 0; kc < NCHUNK; kc++) {
        const int s = kc % NSTG;
        if (kc == NCHUNK - 1) cp_wait<0>(); else cp_wait<1>();
        __syncthreads();
        if (kc + 2 < NCHUNK) issue(kc + 2, (kc + 2) % NSTG);

        const uint32_t ab = sb + (s * GSTG) * 2;
        const uint32_t bb = sb + ((NSTG + s) * GSTG) * 2;
        #pragma unroll
        for (int kccr = 0; kccr < 4; kccr++) {
            const int kk = ((kccr + wrot) & 3) * 16;   // rotated address offset
            uint32_t a[2][4];
            #pragma unroll
            for (int mt = 0; mt < 2; mt++) {
                int row = moff + mt * 16 + arow;
                ldsm4(ab + (row * GLD + kk + acol) * 2,
                      a[mt][0], a[mt][1], a[mt][2], a[mt][3]);
            }
            #pragma unroll
            for (int np = 0; np < 4; np++) {
                uint32_t b0, b1, b2, b3;
                int row = noff + np * 16 + brow;
                ldsm4(bb + (row * GLD + kk + bcol) * 2, b0, b1, b2, b3);
                uint32_t bl[2] = { b0, b1 }, bh[2] = { b2, b3 };
                #pragma unroll
                for (int mt = 0; mt < 2; mt++) {
                    mma_f16(d[mt][2 * np],     a[mt], bl);
                    mma_f16(d[mt][2 * np + 1], a[mt], bh);
                }
            }
        }
    }

    #pragma unroll
    for (int mt = 0; mt < 2; mt++) {
        int row = bm + moff + mt * 16 + g;
        #pragma unroll
        for (int nt = 0; nt < 8; nt++) {
            int col = bn + noff + nt * 8 + 2 * c;
            float2 bv2 = *(const float2*)(bias + col);
            __half2 lo = __floats2half2_rn((d[mt][nt][0] + bv2.x) * scale,
                                           (d[mt][nt][1] + bv2.y) * scale);
            __half2 hi = __floats2half2_rn((d[mt][nt][2] + bv2.x) * scale,
                                           (d[mt][nt][3] + bv2.y) * scale);
            *(__half2*)(out + (size_t)row * H_ + col)       = lo;
            *(__half2*)(out + (size_t)(row + 8) * H_ + col) = hi;
        }
    }
}

// ===========================================================================
// Flash attention — byte-exact R15 (measured 336.5us total with R11 GEMM):
// 64-row Q tile, 128 thr, 4 warps x 16 rows, single-barrier double-buffered
// cp.async, l via ones-MMA, P via ex2.approx.f16x2, skip-rescale.
// NO per-warp rotations (runtime-indexed register arrays spill — R16 lesson).
// ===========================================================================
#define LQH 72

__global__ __launch_bounds__(128) void attn_fp16(float* __restrict__ out)
{
    __shared__ __align__(16) __half Qs[64 * LQH];
    __shared__ __align__(16) __half Ks[2][64 * LQH];
    __shared__ __align__(16) __half Vs[2][64 * LQH];
    __shared__ float Ms[2][64];

    const int tid  = threadIdx.x;
    const int lane = tid & 31;
    const int wid  = tid >> 5;
    const int qb   = (T_ / 64 - 1) - blockIdx.x;   // reversed: heavy first
    const int h    = blockIdx.y;
    const int b    = blockIdx.z;
    const int g    = lane >> 2;
    const int c    = lane & 3;
    const int qrow0 = qb * 64 + wid * 16 + g;

    const uint32_t qs_base = (uint32_t)__cvta_generic_to_shared(Qs);
    const uint32_t ks_base = (uint32_t)__cvta_generic_to_shared(&Ks[0][0]);
    const uint32_t vs_base = (uint32_t)__cvta_generic_to_shared(&Vs[0][0]);
    const uint32_t ms_base = (uint32_t)__cvta_generic_to_shared(&Ms[0][0]);
    const int arow = ((lane >> 3) & 1) * 8 + (lane & 7);
    const int acol = (lane >> 4) * 8;
    const int brow = ((lane >> 4) << 3) + (lane & 7);
    const int bcol = ((lane >> 3) & 1) * 8;

    const size_t hdoff = (size_t)(b * T_) * H_ + h * HD_;
    const __half* kgb = g_K + hdoff;
    const __half* vgb = g_V + hdoff;

    auto issue = [&](int kb, int buf) {
        const __half* kg = kgb + (size_t)kb * 64 * H_;
        const __half* vg = vgb + (size_t)kb * 64 * H_;
        const uint32_t koff = ks_base + buf * (64 * LQH * 2);
        const uint32_t voff = vs_base + buf * (64 * LQH * 2);
        #pragma unroll
        for (int i = 0; i < 4; i++) {
            int u = tid + 128 * i;
            int row = u >> 3, c8 = u & 7;
            cp16(koff + (row * LQH + c8 * 8) * 2, kg + (size_t)row * H_ + c8 * 8);
            cp16(voff + (row * LQH + c8 * 8) * 2, vg + (size_t)row * H_ + c8 * 8);
        }
        if (tid < 64)
            cp4(ms_base + (buf * 64 + tid) * 4, g_ML + (size_t)b * T_ + kb * 64 + tid);
        cp_commit();
    };

    const __half* qg = g_Q + hdoff + (size_t)qb * 64 * H_;
    issue(0, 0);
    #pragma unroll
    for (int i = 0; i < 4; i++) {
        int idx = tid + 128 * i;
        int row = idx >> 3, c8 = idx & 7;
        *(uint4*)&Qs[row * LQH + c8 * 8] =
            *(const uint4*)(qg + (size_t)row * H_ + c8 * 8);
    }
    __syncthreads();

    uint32_t qa[4][4];
    #pragma unroll
    for (int kc = 0; kc < 4; kc++)
        ldsm4(qs_base + ((wid * 16 + arow) * LQH + kc * 16 + acol) * 2,
              qa[kc][0], qa[kc][1], qa[kc][2], qa[kc][3]);

    float o[8][4];
    #pragma unroll
    for (int nt = 0; nt < 8; nt++)
        #pragma unroll
        for (int e = 0; e < 4; e++) o[nt][e] = 0.f;
    float lacc[4] = { 0.f, 0.f, 0.f, 0.f };
    float m0 = -1e30f, m1 = -1e30f;
    const uint32_t onesb[2] = { ONES2, ONES2 };

    for (int kb = 0; kb <= qb; kb++) {
        const int buf = kb & 1;
        cp_wait<0>();
        __syncthreads();
        if (kb < qb) issue(kb + 1, buf ^ 1);

        const uint32_t kbb = ks_base + buf * (64 * LQH * 2);
        const uint32_t vbb = vs_base + buf * (64 * LQH * 2);
        const float* MsB = Ms[buf];

        // ---- S = Q K^T ----
        float s[8][4];
        #pragma unroll
        for (int nt = 0; nt < 8; nt++)
            #pragma unroll
            for (int e = 0; e < 4; e++) s[nt][e] = 0.f;

        #pragma unroll
        for (int kc = 0; kc < 4; kc++) {
            const int kk = kc * 16;
            #pragma unroll
            for (int np = 0; np < 4; np++) {
                uint32_t b0, b1, b2, b3;
                ldsm4(kbb + ((np * 16 + brow) * LQH + kk + bcol) * 2, b0, b1, b2, b3);
                uint32_t bl[2] = { b0, b1 }, bh[2] = { b2, b3 };
                mma_f16(s[2 * np],     qa[kc], bl);
                mma_f16(s[2 * np + 1], qa[kc], bh);
            }
        }

        // ---- mask + online softmax (exp2 domain) ----
        float rmax0 = -1e30f, rmax1 = -1e30f;
        #pragma unroll
        for (int nt = 0; nt < 8; nt++) {
            int lc = nt * 8 + 2 * c;
            float mk0 = MsB[lc], mk1 = MsB[lc + 1];
            s[nt][0] += mk0; s[nt][1] += mk1;
            s[nt][2] += mk0; s[nt][3] += mk1;
            if (kb == qb) {
                int col = kb * 64 + lc;
                if (col     > qrow0)     s[nt][0] = -1e30f;
                if (col + 1 > qrow0)     s[nt][1] = -1e30f;
                if (col     > qrow0 + 8) s[nt][2] = -1e30f;
                if (col + 1 > qrow0 + 8) s[nt][3] = -1e30f;
            }
            rmax0 = fmaxf(rmax0, fmaxf(s[nt][0], s[nt][1]));
            rmax1 = fmaxf(rmax1, fmaxf(s[nt][2], s[nt][3]));
        }
        rmax0 = fmaxf(rmax0, __shfl_xor_sync(0xffffffffu, rmax0, 1));
        rmax0 = fmaxf(rmax0, __shfl_xor_sync(0xffffffffu, rmax0, 2));
        rmax1 = fmaxf(rmax1, __shfl_xor_sync(0xffffffffu, rmax1, 1));
        rmax1 = fmaxf(rmax1, __shfl_xor_sync(0xffffffffu, rmax1, 2));

        float mn0 = fmaxf(m0, rmax0), mn1 = fmaxf(m1, rmax1);
        if (__any_sync(0xffffffffu, (mn0 > m0) | (mn1 > m1))) {
            float cr0 = exp2f(m0 - mn0), cr1 = exp2f(m1 - mn1);
            #pragma unroll
            for (int nt = 0; nt < 8; nt++) {
                o[nt][0] *= cr0; o[nt][1] *= cr0;
                o[nt][2] *= cr1; o[nt][3] *= cr1;
            }
            lacc[0] *= cr0; lacc[2] *= cr1;
            m0 = mn0; m1 = mn1;
        }

        // ---- P = 2^(s-m) directly in fp16 pairs ----
        uint32_t ph[8][2];
        #pragma unroll
        for (int nt = 0; nt < 8; nt++) {
            __half2 t01 = __floats2half2_rn(s[nt][0] - m0, s[nt][1] - m0);
            __half2 t23 = __floats2half2_rn(s[nt][2] - m1, s[nt][3] - m1);
            ph[nt][0] = h2exp2(*(uint32_t*)&t01);
            ph[nt][1] = h2exp2(*(uint32_t*)&t23);
        }

        // ---- O += P V ; l += P * ones ----
        #pragma unroll
        for (int jc = 0; jc < 4; jc++) {
            uint32_t a[4] = { ph[2 * jc][0], ph[2 * jc][1],
                              ph[2 * jc + 1][0], ph[2 * jc + 1][1] };
            mma_f16(lacc, a, onesb);
            #pragma unroll
            for (int dp = 0; dp < 4; dp++) {
                uint32_t b0, b1, b2, b3;
                ldsm4t(vbb + ((jc * 16 + arow) * LQH + dp * 16 + acol) * 2,
                       b0, b1, b2, b3);
                uint32_t bl[2] = { b0, b1 }, bh[2] = { b2, b3 };
                mma_f16(o[2 * dp],     a, bl);
                mma_f16(o[2 * dp + 1], a, bh);
            }
        }
    }

    float inv0 = 1.f / lacc[0], inv1 = 1.f / lacc[2];
    float* og = out + ((size_t)(b * T_) + (size_t)qb * 64 + wid * 16 + g) * H_ + h * HD_;
    #pragma unroll
    for (int nt = 0; nt < 8; nt++) {
        int lc = nt * 8 + 2 * c;
        float2 w0, w1;
        w0.x = o[nt][0] * inv0; w0.y = o[nt][1] * inv0;
        w1.x = o[nt][2] * inv1; w1.y = o[nt][3] * inv1;
        *(float2*)(og + lc)          = w0;
        *(float2*)(og + 8 * H_ + lc) = w1;
    }
}

// ===========================================================================
// Launch
// ===========================================================================
extern "C" void kernel_launch(void* const* d_in, const int* in_sizes, int n_in,
                              void* d_out, int out_size)
{
    const float* x    = (const float*)d_in[0];
    const float* mask = (const float*)d_in[1];
    const float* Wq   = (const float*)d_in[2];
    const float* bq   = (const float*)d_in[3];
    const float* Wk   = (const float*)d_in[4];
    const float* bk   = (const float*)d_in[5];
    const float* Wv   = (const float*)d_in[6];
    const float* bv   = (const float*)d_in[7];
    float* out = (float*)d_out;

    __half *X16p;
    cudaGetSymbolAddress((void**)&X16p, g_X16);

    cudaFuncSetAttribute(qkv_gemm_fp16, cudaFuncAttributeMaxDynamicSharedMemorySize,
                         GEMM_SMEM);

    cvtX<<<(M_ * H_ / 8 + 255) / 256, 256>>>(x, X16p, M_ * H_ / 8);
    dim3 wgrid(H_ * H_ / 8 / 256, 1, 3);
    cvtW<<<wgrid, 256>>>(Wq, Wk, Wv);
    prepMask<<<B_ * T_ / 256, 256>>>(mask);

    dim3 ggrid(H_ / 128, M_ / 128, 3);   // (8, 64, 3)
    qkv_gemm_fp16<<<ggrid, 256, GEMM_SMEM>>>(bq, bk, bv);

    dim3 agrid(T_ / 64, NH_, B_);        // (32, 16, 4)
    attn_fp16<<<agrid, 128>>>(out);
}